// round 5
// baseline (speedup 1.0000x reference)
#include <cuda_runtime.h>
#include <cuda_bf16.h>
#include <math.h>
#include <stdint.h>

#define B_  8
#define L_  4096
#define D_  1024
#define K_  256
#define N3_ 3072    // 3*D
#define BL_ (B_*L_)
#define K3_ 3072    // gemm1 reduction: [hi | lo | hi]
#define L3_ (3*L_)  // 12288
#define D3_ (3*D_)  // 3072
#define KC3_ (3*K_) // 768

typedef __nv_bfloat16 bf16;

// ---------------- scratch (__device__ globals) -----------------------------
__device__ float g_qkv[(size_t)BL_ * N3_];          // k,v fp32 (q region unused)
__device__ float g_sc [(size_t)BL_ * K_];           // scores fp32
__device__ bf16  g_xs [(size_t)BL_ * K3_];          // x: [h|l|h]
__device__ bf16  g_wts[(size_t)N3_ * K3_];          // W^T: [wh|wh|wl]
__device__ bf16  g_qs [(size_t)BL_ * D3_];          // q split A-style [h|l|h]
__device__ bf16  g_kTs[(size_t)B_ * D_ * L3_];      // k^T split B-style [h|h|l]
__device__ bf16  g_vTs[(size_t)B_ * D_ * L3_];      // v^T split A-style [h|l|h]
__device__ bf16  g_HkT[(size_t)K_ * L3_];           // Hk^T split A-style
__device__ bf16  g_HvT[(size_t)K_ * L3_];           // Hv^T split B-style
__device__ bf16  g_Ks [(size_t)B_ * K_ * D3_];      // K_proj split B-style (along d)
__device__ bf16  g_Vs [(size_t)B_ * D_ * KC3_];     // V_proj^T split B-style (along kc)
__device__ bf16  g_Ps [(size_t)BL_ * KC3_];         // weights split A-style (along kc)

// ---------------- helpers --------------------------------------------------
__device__ __forceinline__ uint32_t smem_u32(const void* p) {
    uint32_t a;
    asm("{ .reg .u64 t; cvta.to.shared.u64 t, %1; cvt.u32.u64 %0, t; }" : "=r"(a) : "l"(p));
    return a;
}
__device__ __forceinline__ void ldsm_x4(uint32_t* r, uint32_t addr) {
    asm volatile("ldmatrix.sync.aligned.m8n8.x4.shared.b16 {%0,%1,%2,%3}, [%4];"
                 : "=r"(r[0]), "=r"(r[1]), "=r"(r[2]), "=r"(r[3]) : "r"(addr));
}
__device__ __forceinline__ void mma16816(float* d, const uint32_t* a, uint32_t b0, uint32_t b1) {
    asm volatile("mma.sync.aligned.m16n8k16.row.col.f32.bf16.bf16.f32 "
                 "{%0,%1,%2,%3}, {%4,%5,%6,%7}, {%8,%9}, {%0,%1,%2,%3};"
                 : "+f"(d[0]), "+f"(d[1]), "+f"(d[2]), "+f"(d[3])
                 : "r"(a[0]), "r"(a[1]), "r"(a[2]), "r"(a[3]), "r"(b0), "r"(b1));
}
// split helpers: write pair (a,b) as 3 blocks of size blk within one row
__device__ __forceinline__ void split3A(bf16* row, int n, int blk, float a, float b) {
    bf16 h0 = __float2bfloat16_rn(a), h1 = __float2bfloat16_rn(b);
    bf16 l0 = __float2bfloat16_rn(a - __bfloat162float(h0));
    bf16 l1 = __float2bfloat16_rn(b - __bfloat162float(h1));
    *(__nv_bfloat162*)(row + n)           = __nv_bfloat162(h0, h1);
    *(__nv_bfloat162*)(row + blk + n)     = __nv_bfloat162(l0, l1);
    *(__nv_bfloat162*)(row + 2 * blk + n) = __nv_bfloat162(h0, h1);
}
__device__ __forceinline__ void split3B(bf16* row, int n, int blk, float a, float b) {
    bf16 h0 = __float2bfloat16_rn(a), h1 = __float2bfloat16_rn(b);
    bf16 l0 = __float2bfloat16_rn(a - __bfloat162float(h0));
    bf16 l1 = __float2bfloat16_rn(b - __bfloat162float(h1));
    *(__nv_bfloat162*)(row + n)           = __nv_bfloat162(h0, h1);
    *(__nv_bfloat162*)(row + blk + n)     = __nv_bfloat162(h0, h1);
    *(__nv_bfloat162*)(row + 2 * blk + n) = __nv_bfloat162(l0, l1);
}

// ---------------------------------------------------------------------------
// split x -> [hi | lo | hi]
// ---------------------------------------------------------------------------
__global__ __launch_bounds__(256)
void split_x(const float* __restrict__ x, bf16* __restrict__ xs)
{
    size_t chunk = (size_t)blockIdx.x * 256 + threadIdx.x;
    size_t m  = chunk >> 8;
    int    dq = (int)(chunk & 255) * 4;
    float4 v = *(const float4*)(x + m * D_ + dq);
    bf16* row = xs + m * K3_;
    split3A(row, dq,     D_, v.x, v.y);
    split3A(row, dq + 2, D_, v.z, v.w);
}

// ---------------------------------------------------------------------------
// transpose + split W [D, 3D] -> wts [3D, wh | wh | wl]
// ---------------------------------------------------------------------------
__global__ __launch_bounds__(256)
void wsplit(const float* __restrict__ W, bf16* __restrict__ wts)
{
    __shared__ float t[32][33];
    int n = blockIdx.x * 32 + threadIdx.x;
    int d0 = blockIdx.y * 32;
#pragma unroll
    for (int i = threadIdx.y; i < 32; i += 8)
        t[i][threadIdx.x] = W[(size_t)(d0 + i) * N3_ + n];
    __syncthreads();
    int n0 = blockIdx.x * 32;
    int d = d0 + threadIdx.x;
#pragma unroll
    for (int i = threadIdx.y; i < 32; i += 8) {
        float v = t[threadIdx.x][i];
        bf16 h = __float2bfloat16_rn(v);
        bf16 l = __float2bfloat16_rn(v - __bfloat162float(h));
        bf16* row = wts + (size_t)(n0 + i) * K3_;
        row[d] = h; row[D_ + d] = h; row[2 * D_ + d] = l;
    }
}

// ---------------------------------------------------------------------------
// H [L,K] -> H^T split [K, 3L]; z=0: Hk (A-style), z=1: Hv (B-style)
// ---------------------------------------------------------------------------
__global__ __launch_bounds__(256)
void ht_split(const float* __restrict__ Hk, const float* __restrict__ Hv,
              bf16* __restrict__ HkT, bf16* __restrict__ HvT)
{
    int which = blockIdx.z;
    const float* H = which ? Hv : Hk;
    bf16* dst = which ? HvT : HkT;
    __shared__ float t[32][33];
    int l0 = blockIdx.x * 32, k0 = blockIdx.y * 32;
#pragma unroll
    for (int i = threadIdx.y; i < 32; i += 8)
        t[i][threadIdx.x] = H[(size_t)(l0 + i) * K_ + k0 + threadIdx.x];
    __syncthreads();
    int l = l0 + threadIdx.x;
#pragma unroll
    for (int i = threadIdx.y; i < 32; i += 8) {
        int kc = k0 + i;
        float v = t[threadIdx.x][i];
        bf16 h = __float2bfloat16_rn(v);
        bf16 lo = __float2bfloat16_rn(v - __bfloat162float(h));
        bf16* row = dst + (size_t)kc * L3_;
        if (which == 0) { row[l] = h;  row[L_ + l] = lo; row[2 * L_ + l] = h;  }
        else            { row[l] = h;  row[L_ + l] = h;  row[2 * L_ + l] = lo; }
    }
}

// ---------------------------------------------------------------------------
// k,v transpose + split: qkv[b,l,(p+1)*D+d] -> {k^T B-style, v^T A-style}[b,d,3L]
// grid (L/32, D/32, 2B), block (32,8)
// ---------------------------------------------------------------------------
__global__ __launch_bounds__(256)
void kvt_split(const float* __restrict__ qkv, bf16* __restrict__ kTs, bf16* __restrict__ vTs)
{
    int p = blockIdx.z & 1, b = blockIdx.z >> 1;
    __shared__ float t[32][33];
    int l0 = blockIdx.x * 32, d0 = blockIdx.y * 32;
#pragma unroll
    for (int i = threadIdx.y; i < 32; i += 8)
        t[i][threadIdx.x] = qkv[((size_t)b * L_ + l0 + i) * N3_ + (p + 1) * D_ + d0 + threadIdx.x];
    __syncthreads();
    bf16* dst = (p ? vTs : kTs) + (size_t)b * D_ * L3_;
    int l = l0 + threadIdx.x;
#pragma unroll
    for (int i = threadIdx.y; i < 32; i += 8) {
        int d = d0 + i;
        float v = t[threadIdx.x][i];
        bf16 h = __float2bfloat16_rn(v);
        bf16 lo = __float2bfloat16_rn(v - __bfloat162float(h));
        bf16* row = dst + (size_t)d * L3_;
        if (p == 0) { row[l] = h; row[L_ + l] = h;  row[2 * L_ + l] = lo; }   // k: B-style
        else        { row[l] = h; row[L_ + l] = lo; row[2 * L_ + l] = h;  }   // v: A-style
    }
}

// ---------------------------------------------------------------------------
// GEMM1: qkv = x @ W + b. Epilogue: q -> qs split (A-style), k/v -> fp32 qkv
// ---------------------------------------------------------------------------
#define PAD 40

__global__ __launch_bounds__(256, 2)
void gemm1_mma(const bf16* __restrict__ xs, const bf16* __restrict__ ws,
               const float* __restrict__ bias, float* __restrict__ qkv,
               bf16* __restrict__ qs)
{
    __shared__ __align__(16) bf16 As[2][128][PAD];
    __shared__ __align__(16) bf16 Bs[2][128][PAD];

    const int tid = threadIdx.x, lane = tid & 31, warp = tid >> 5;
    const int wm = (warp & 1) * 64, wn = (warp >> 1) * 32;
    const int m0 = blockIdx.y * 128, n0 = blockIdx.x * 128;

    const uint32_t aB = smem_u32(&As[0][0][0]);
    const uint32_t bB = smem_u32(&Bs[0][0][0]);
    const int larow = lane & 15, lacol = (lane >> 4) * 8;

    float acc[4][4][4] = {};

    uint4 pa[2], pb[2];
#pragma unroll
    for (int i = 0; i < 2; i++) {
        int idx = tid + i * 256;
        int row = idx >> 2, c = (idx & 3) * 8;
        pa[i] = *(const uint4*)(xs + (size_t)(m0 + row) * K3_ + c);
        pb[i] = *(const uint4*)(ws + (size_t)(n0 + row) * K3_ + c);
    }
#pragma unroll
    for (int i = 0; i < 2; i++) {
        int idx = tid + i * 256;
        int row = idx >> 2, c = (idx & 3) * 8;
        *(uint4*)(&As[0][row][c]) = pa[i];
        *(uint4*)(&Bs[0][row][c]) = pb[i];
    }
    __syncthreads();

    const int NSTEP = K3_ / 32;
    for (int s = 0; s < NSTEP; s++) {
        const int buf = s & 1;
        if (s + 1 < NSTEP) {
            int kc = (s + 1) * 32;
#pragma unroll
            for (int i = 0; i < 2; i++) {
                int idx = tid + i * 256;
                int row = idx >> 2, c = (idx & 3) * 8;
                pa[i] = *(const uint4*)(xs + (size_t)(m0 + row) * K3_ + kc + c);
                pb[i] = *(const uint4*)(ws + (size_t)(n0 + row) * K3_ + kc + c);
            }
        }
#pragma unroll
        for (int kk = 0; kk < 32; kk += 16) {
            uint32_t a[4][4], b[2][4];
#pragma unroll
            for (int mi = 0; mi < 4; mi++)
                ldsm_x4(a[mi], aB + (uint32_t)(((buf * 128 + wm + mi * 16 + larow) * PAD) + kk + lacol) * 2);
#pragma unroll
            for (int nj = 0; nj < 2; nj++)
                ldsm_x4(b[nj], bB + (uint32_t)(((buf * 128 + wn + nj * 16 + larow) * PAD) + kk + lacol) * 2);
#pragma unroll
            for (int mi = 0; mi < 4; mi++)
#pragma unroll
                for (int ni = 0; ni < 4; ni++)
                    mma16816(acc[mi][ni], a[mi], b[ni >> 1][ni & 1], b[ni >> 1][(ni & 1) + 2]);
        }
        if (s + 1 < NSTEP) {
            int ob = (s + 1) & 1;
#pragma unroll
            for (int i = 0; i < 2; i++) {
                int idx = tid + i * 256;
                int row = idx >> 2, c = (idx & 3) * 8;
                *(uint4*)(&As[ob][row][c]) = pa[i];
                *(uint4*)(&Bs[ob][row][c]) = pb[i];
            }
        }
        __syncthreads();
    }

    const bool is_q = (n0 < D_);
#pragma unroll
    for (int mi = 0; mi < 4; mi++) {
#pragma unroll
        for (int ni = 0; ni < 4; ni++) {
            int n = n0 + wn + ni * 8 + (lane & 3) * 2;
            float2 bv = *(const float2*)(bias + n);
            int m = m0 + wm + mi * 16 + (lane >> 2);
            float v00 = acc[mi][ni][0] + bv.x, v01 = acc[mi][ni][1] + bv.y;
            float v10 = acc[mi][ni][2] + bv.x, v11 = acc[mi][ni][3] + bv.y;
            if (is_q) {
                split3A(qs + (size_t)m * D3_,       n, D_, v00, v01);
                split3A(qs + (size_t)(m + 8) * D3_, n, D_, v10, v11);
            } else {
                float* p0 = qkv + (size_t)m * N3_ + n;
                float* p1 = qkv + (size_t)(m + 8) * N3_ + n;
                p0[0] = v00; p0[1] = v01;
                p1[0] = v10; p1[1] = v11;
            }
        }
    }
}

// ---------------------------------------------------------------------------
// Generic NT mma GEMM, 128x128 tile, batched via z.
// MODE 0: fp32 out (x scale).  MODE 1: bf16 split3-B out (blocks of ncs).
// ---------------------------------------------------------------------------
template<int MODE>
__global__ __launch_bounds__(256, 2)
void mma_nt(const bf16* __restrict__ A, long sA, int lda,
            const bf16* __restrict__ Bm, long sB, int ldb,
            int Kred, float scale,
            float* __restrict__ Cf, long sCf, int ldc,
            bf16* __restrict__ Cs, long sCs, int ncs)
{
    __shared__ __align__(16) bf16 As[2][128][PAD];
    __shared__ __align__(16) bf16 Bs[2][128][PAD];

    const int tid = threadIdx.x, lane = tid & 31, warp = tid >> 5;
    const int wm = (warp & 1) * 64, wn = (warp >> 1) * 32;
    const int m0 = blockIdx.y * 128, n0 = blockIdx.x * 128;

    const bf16* Ab = A  + (size_t)blockIdx.z * sA;
    const bf16* Bb = Bm + (size_t)blockIdx.z * sB;

    const uint32_t aB = smem_u32(&As[0][0][0]);
    const uint32_t bB = smem_u32(&Bs[0][0][0]);
    const int larow = lane & 15, lacol = (lane >> 4) * 8;

    float acc[4][4][4] = {};

    uint4 pa[2], pb[2];
#pragma unroll
    for (int i = 0; i < 2; i++) {
        int idx = tid + i * 256;
        int row = idx >> 2, c = (idx & 3) * 8;
        pa[i] = *(const uint4*)(Ab + (size_t)(m0 + row) * lda + c);
        pb[i] = *(const uint4*)(Bb + (size_t)(n0 + row) * ldb + c);
    }
#pragma unroll
    for (int i = 0; i < 2; i++) {
        int idx = tid + i * 256;
        int row = idx >> 2, c = (idx & 3) * 8;
        *(uint4*)(&As[0][row][c]) = pa[i];
        *(uint4*)(&Bs[0][row][c]) = pb[i];
    }
    __syncthreads();

    const int NSTEP = Kred / 32;
    for (int s = 0; s < NSTEP; s++) {
        const int buf = s & 1;
        if (s + 1 < NSTEP) {
            int kc = (s + 1) * 32;
#pragma unroll
            for (int i = 0; i < 2; i++) {
                int idx = tid + i * 256;
                int row = idx >> 2, c = (idx & 3) * 8;
                pa[i] = *(const uint4*)(Ab + (size_t)(m0 + row) * lda + kc + c);
                pb[i] = *(const uint4*)(Bb + (size_t)(n0 + row) * ldb + kc + c);
            }
        }
#pragma unroll
        for (int kk = 0; kk < 32; kk += 16) {
            uint32_t a[4][4], b[2][4];
#pragma unroll
            for (int mi = 0; mi < 4; mi++)
                ldsm_x4(a[mi], aB + (uint32_t)(((buf * 128 + wm + mi * 16 + larow) * PAD) + kk + lacol) * 2);
#pragma unroll
            for (int nj = 0; nj < 2; nj++)
                ldsm_x4(b[nj], bB + (uint32_t)(((buf * 128 + wn + nj * 16 + larow) * PAD) + kk + lacol) * 2);
#pragma unroll
            for (int mi = 0; mi < 4; mi++)
#pragma unroll
                for (int ni = 0; ni < 4; ni++)
                    mma16816(acc[mi][ni], a[mi], b[ni >> 1][ni & 1], b[ni >> 1][(ni & 1) + 2]);
        }
        if (s + 1 < NSTEP) {
            int ob = (s + 1) & 1;
#pragma unroll
            for (int i = 0; i < 2; i++) {
                int idx = tid + i * 256;
                int row = idx >> 2, c = (idx & 3) * 8;
                *(uint4*)(&As[ob][row][c]) = pa[i];
                *(uint4*)(&Bs[ob][row][c]) = pb[i];
            }
        }
        __syncthreads();
    }

#pragma unroll
    for (int mi = 0; mi < 4; mi++) {
#pragma unroll
        for (int ni = 0; ni < 4; ni++) {
            int n = n0 + wn + ni * 8 + (lane & 3) * 2;
            int m = m0 + wm + mi * 16 + (lane >> 2);
            if (MODE == 0) {
                float* base = Cf + (size_t)blockIdx.z * sCf;
                float* p0 = base + (size_t)m * ldc + n;
                float* p1 = base + (size_t)(m + 8) * ldc + n;
                p0[0] = acc[mi][ni][0] * scale; p0[1] = acc[mi][ni][1] * scale;
                p1[0] = acc[mi][ni][2] * scale; p1[1] = acc[mi][ni][3] * scale;
            } else {
                bf16* base = Cs + (size_t)blockIdx.z * sCs;
                split3B(base + (size_t)m * 3 * ncs,       n, ncs, acc[mi][ni][0], acc[mi][ni][1]);
                split3B(base + (size_t)(m + 8) * 3 * ncs, n, ncs, acc[mi][ni][2], acc[mi][ni][3]);
            }
        }
    }
}

// ---------------------------------------------------------------------------
// softmax over K=256 -> weights split A-style [Ph | Pl | Ph]
// ---------------------------------------------------------------------------
__global__ __launch_bounds__(256)
void softmax_ps(const float* __restrict__ S, bf16* __restrict__ Ps)
{
    int warp = threadIdx.x >> 5, lane = threadIdx.x & 31;
    size_t row = (size_t)blockIdx.x * 8 + warp;
    const float* p = S + row * K_;

    float v[8];
    float m = -INFINITY;
#pragma unroll
    for (int i = 0; i < 8; i++) {
        v[i] = p[lane + i * 32];
        m = fmaxf(m, v[i]);
    }
#pragma unroll
    for (int o = 16; o > 0; o >>= 1) m = fmaxf(m, __shfl_xor_sync(0xffffffffu, m, o));

    float s = 0.f;
#pragma unroll
    for (int i = 0; i < 8; i++) { v[i] = __expf(v[i] - m); s += v[i]; }
#pragma unroll
    for (int o = 16; o > 0; o >>= 1) s += __shfl_xor_sync(0xffffffffu, s, o);

    float inv = 1.f / s;
    bf16* r = Ps + row * KC3_;
#pragma unroll
    for (int i = 0; i < 8; i++) {
        int kc = lane + i * 32;
        float w = v[i] * inv;
        bf16 h = __float2bfloat16_rn(w);
        bf16 lo = __float2bfloat16_rn(w - __bfloat162float(h));
        r[kc] = h; r[K_ + kc] = lo; r[2 * K_ + kc] = h;
    }
}

// ---------------------------------------------------------------------------
extern "C" void kernel_launch(void* const* d_in, const int* in_sizes, int n_in,
                              void* d_out, int out_size)
{
    const float* x    = (const float*)d_in[0];
    const float* W    = (const float*)d_in[1];
    const float* bias = (const float*)d_in[2];
    const float* Hk   = (const float*)d_in[3];
    const float* Hv   = (const float*)d_in[4];
    float*       out  = (float*)d_out;

    float *qkv, *sc;
    bf16 *xs, *wts, *qs, *kTs, *vTs, *HkT, *HvT, *Ks, *Vs, *Ps;
    cudaGetSymbolAddress((void**)&qkv, g_qkv);
    cudaGetSymbolAddress((void**)&sc,  g_sc);
    cudaGetSymbolAddress((void**)&xs,  g_xs);
    cudaGetSymbolAddress((void**)&wts, g_wts);
    cudaGetSymbolAddress((void**)&qs,  g_qs);
    cudaGetSymbolAddress((void**)&kTs, g_kTs);
    cudaGetSymbolAddress((void**)&vTs, g_vTs);
    cudaGetSymbolAddress((void**)&HkT, g_HkT);
    cudaGetSymbolAddress((void**)&HvT, g_HvT);
    cudaGetSymbolAddress((void**)&Ks,  g_Ks);
    cudaGetSymbolAddress((void**)&Vs,  g_Vs);
    cudaGetSymbolAddress((void**)&Ps,  g_Ps);

    // 0) input preprocessing
    split_x<<<(size_t)BL_ * D_ / (256 * 4), 256>>>(x, xs);
    wsplit<<<dim3(N3_ / 32, D_ / 32), dim3(32, 8)>>>(W, wts);
    ht_split<<<dim3(L_ / 32, K_ / 32, 2), dim3(32, 8)>>>(Hk, Hv, HkT, HvT);

    // 1) qkv GEMM (tensor cores); q emitted pre-split
    gemm1_mma<<<dim3(N3_ / 128, BL_ / 128), 256>>>(xs, wts, bias, qkv, qs);

    // 1b) transpose+split k, v
    kvt_split<<<dim3(L_ / 32, D_ / 32, 2 * B_), dim3(32, 8)>>>(qkv, kTs, vTs);

    // 2) K_proj[kc,d] = HkT @ kT   (M=256, N=1024, Kred=3L) -> Ks split
    mma_nt<1><<<dim3(D_ / 128, K_ / 128, B_), 256>>>(
        HkT, 0L, L3_, kTs, (long)D_ * L3_, L3_, L3_, 1.f,
        nullptr, 0L, 0, Ks, (long)K_ * D3_, D_);

    // 2') V_projT[d,kc] = vT @ HvT (M=1024, N=256, Kred=3L) -> Vs split
    mma_nt<1><<<dim3(K_ / 128, D_ / 128, B_), 256>>>(
        vTs, (long)D_ * L3_, L3_, HvT, 0L, L3_, L3_, 1.f,
        nullptr, 0L, 0, Vs, (long)D_ * KC3_, K_);

    // 3) scores[l,kc] = qs @ Ks / 32   (M=4096, N=256, Kred=3D)
    mma_nt<0><<<dim3(K_ / 128, L_ / 128, B_), 256>>>(
        qs, (long)L_ * D3_, D3_, Ks, (long)K_ * D3_, D3_, D3_, 0.03125f,
        sc, (long)L_ * K_, K_, nullptr, 0L, 0);

    // 4) softmax -> Ps split
    softmax_ps<<<BL_ / 8, 256>>>(sc, Ps);

    // 5) out[l,d] = Ps @ Vs   (M=4096, N=1024, Kred=3K)
    mma_nt<0><<<dim3(D_ / 128, L_ / 128, B_), 256>>>(
        Ps, (long)L_ * KC3_, KC3_, Vs, (long)D_ * KC3_, KC3_, KC3_, 1.f,
        out, (long)L_ * D_, D_, nullptr, 0L, 0);
}

// round 6
// speedup vs baseline: 1.5586x; 1.5586x over previous
#include <cuda_runtime.h>
#include <cuda_bf16.h>
#include <math.h>
#include <stdint.h>

#define B_  8
#define L_  4096
#define D_  1024
#define K_  256
#define N3_ 3072
#define BL_ (B_*L_)

typedef __nv_bfloat16 bf16;

// ---------------- scratch ---------------------------------------------------
__device__ float g_qkv[(size_t)BL_ * N3_];     // [B,L,3D] fp32
__device__ float g_sc [(size_t)BL_ * K_];      // [B,L,K]  fp32
__device__ float g_kp [(size_t)B_ * K_ * D_];  // K_proj [b,kc,d]
__device__ float g_vp [(size_t)B_ * K_ * D_];  // V_proj [b,kc,d]

// ---------------- helpers ---------------------------------------------------
__device__ __forceinline__ uint32_t smem_u32(const void* p) {
    uint32_t a;
    asm("{ .reg .u64 t; cvta.to.shared.u64 t, %1; cvt.u32.u64 %0, t; }" : "=r"(a) : "l"(p));
    return a;
}
__device__ __forceinline__ void ldsm_x4(uint32_t* r, uint32_t addr) {
    asm volatile("ldmatrix.sync.aligned.m8n8.x4.shared.b16 {%0,%1,%2,%3}, [%4];"
                 : "=r"(r[0]), "=r"(r[1]), "=r"(r[2]), "=r"(r[3]) : "r"(addr));
}
__device__ __forceinline__ void ldsm_x4t(uint32_t* r, uint32_t addr) {
    asm volatile("ldmatrix.sync.aligned.m8n8.x4.trans.shared.b16 {%0,%1,%2,%3}, [%4];"
                 : "=r"(r[0]), "=r"(r[1]), "=r"(r[2]), "=r"(r[3]) : "r"(addr));
}
__device__ __forceinline__ void mma16816(float* d, const uint32_t* a, uint32_t b0, uint32_t b1) {
    asm volatile("mma.sync.aligned.m16n8k16.row.col.f32.bf16.bf16.f32 "
                 "{%0,%1,%2,%3}, {%4,%5,%6,%7}, {%8,%9}, {%0,%1,%2,%3};"
                 : "+f"(d[0]), "+f"(d[1]), "+f"(d[2]), "+f"(d[3])
                 : "r"(a[0]), "r"(a[1]), "r"(a[2]), "r"(a[3]), "r"(b0), "r"(b1));
}
// float2 -> packed hi bf16x2 + lo bf16x2
__device__ __forceinline__ void cvt_hl(float a, float b, uint32_t& h, uint32_t& l) {
    __nv_bfloat162 hv = __floats2bfloat162_rn(a, b);
    float2 hf = __bfloat1622float2(hv);
    __nv_bfloat162 lv = __floats2bfloat162_rn(a - hf.x, b - hf.y);
    h = *(uint32_t*)&hv;
    l = *(uint32_t*)&lv;
}

// ---------------------------------------------------------------------------
// Unified split-on-the-fly bf16x3 mma GEMM.
//   C[m,n] (+= bias[n]) = scale * sum_k A.B
//   TRA=0: A gmem [m][k] (k contig).  TRA=1: A gmem [k][m] (m contig).
//   TRB=0: B gmem [n][k] (k contig).  TRB=1: B gmem [k][n] (n contig).
// CTA tile 128x128, BK=32 fp32, double-buffered smem, batched via blockIdx.z.
// ---------------------------------------------------------------------------
#define PADN 40    // non-trans row pitch (bf16 elems)
#define PADT 136   // trans row pitch

template<int TRA, int TRB>
__global__ __launch_bounds__(256, 2)
void gsplit(const float* __restrict__ A, int lda, long strA,
            const float* __restrict__ Bm, int ldb, long strB,
            float* __restrict__ C, int ldc, long strC,
            int Kred, float scale, const float* __restrict__ bias)
{
    extern __shared__ char smem[];
    constexpr int SAe = TRA ? 32 * PADT : 128 * PADN;   // elems per tile
    constexpr int SBe = TRB ? 32 * PADT : 128 * PADN;
    constexpr int STE = 2 * SAe + 2 * SBe;              // elems per stage

    const int tid = threadIdx.x, lane = tid & 31, warp = tid >> 5;
    const int wm = (warp & 1) * 64, wn = (warp >> 1) * 32;
    const int m0 = blockIdx.y * 128, n0 = blockIdx.x * 128;

    const float* Ab = A  + (size_t)blockIdx.z * strA;
    const float* Bb = Bm + (size_t)blockIdx.z * strB;

    bf16* s0 = (bf16*)smem;
    const uint32_t sbase = smem_u32(s0);

    // ldmatrix lane addressing
    const int nt_row = lane & 15, nt_col = (lane >> 4) * 8;              // non-trans
    const int tr_krow = (lane & 7) + ((lane & 16) >> 1);                 // trans
    const int tr_mcol = lane & 8;

    float acc[4][4][4] = {};
    float4 pa[4], pb[4];

    // ---- gmem load of one k-tile into regs ----
    auto loadA = [&](int k0) {
#pragma unroll
        for (int i = 0; i < 4; i++) {
            int idx = tid + i * 256;
            if (TRA) { int kr = idx >> 5, c = (idx & 31) * 4;
                pa[i] = *(const float4*)(Ab + (size_t)(k0 + kr) * lda + m0 + c); }
            else     { int r = idx >> 3, c = (idx & 7) * 4;
                pa[i] = *(const float4*)(Ab + (size_t)(m0 + r) * lda + k0 + c); }
        }
    };
    auto loadB = [&](int k0) {
#pragma unroll
        for (int i = 0; i < 4; i++) {
            int idx = tid + i * 256;
            if (TRB) { int kr = idx >> 5, c = (idx & 31) * 4;
                pb[i] = *(const float4*)(Bb + (size_t)(k0 + kr) * ldb + n0 + c); }
            else     { int r = idx >> 3, c = (idx & 7) * 4;
                pb[i] = *(const float4*)(Bb + (size_t)(n0 + r) * ldb + k0 + c); }
        }
    };
    // ---- convert + store regs into stage buf ----
    auto storeA = [&](int buf) {
        bf16* sh = s0 + buf * STE;
        bf16* sl = sh + SAe;
#pragma unroll
        for (int i = 0; i < 4; i++) {
            int idx = tid + i * 256;
            uint32_t h0, l0, h1, l1;
            cvt_hl(pa[i].x, pa[i].y, h0, l0);
            cvt_hl(pa[i].z, pa[i].w, h1, l1);
            int off;
            if (TRA) { int kr = idx >> 5, c = (idx & 31) * 4; off = kr * PADT + c; }
            else     { int r = idx >> 3,  c = (idx & 7) * 4;  off = r * PADN + c; }
            *(uint2*)(sh + off) = make_uint2(h0, h1);
            *(uint2*)(sl + off) = make_uint2(l0, l1);
        }
    };
    auto storeB = [&](int buf) {
        bf16* sh = s0 + buf * STE + 2 * SAe;
        bf16* sl = sh + SBe;
#pragma unroll
        for (int i = 0; i < 4; i++) {
            int idx = tid + i * 256;
            uint32_t h0, l0, h1, l1;
            cvt_hl(pb[i].x, pb[i].y, h0, l0);
            cvt_hl(pb[i].z, pb[i].w, h1, l1);
            int off;
            if (TRB) { int kr = idx >> 5, c = (idx & 31) * 4; off = kr * PADT + c; }
            else     { int r = idx >> 3,  c = (idx & 7) * 4;  off = r * PADN + c; }
            *(uint2*)(sh + off) = make_uint2(h0, h1);
            *(uint2*)(sl + off) = make_uint2(l0, l1);
        }
    };

    loadA(0); loadB(0);
    storeA(0); storeB(0);
    __syncthreads();

    const int NSTEP = Kred / 32;
    for (int s = 0; s < NSTEP; s++) {
        const int buf = s & 1;
        if (s + 1 < NSTEP) { loadA((s + 1) * 32); loadB((s + 1) * 32); }

        const uint32_t aH = sbase + (uint32_t)(buf * STE) * 2;
        const uint32_t aL = aH + SAe * 2;
        const uint32_t bH = aH + 2 * SAe * 2;
        const uint32_t bL = bH + SBe * 2;

#pragma unroll
        for (int kk = 0; kk < 32; kk += 16) {
            uint32_t bh[2][4], bl[2][4];
#pragma unroll
            for (int nj = 0; nj < 2; nj++) {
                if (TRB) {
                    uint32_t off = (uint32_t)((kk + tr_krow) * PADT + wn + nj * 16 + tr_mcol) * 2;
                    ldsm_x4t(bh[nj], bH + off);
                    ldsm_x4t(bl[nj], bL + off);
                } else {
                    uint32_t off = (uint32_t)((wn + nj * 16 + nt_row) * PADN + kk + nt_col) * 2;
                    ldsm_x4(bh[nj], bH + off);
                    ldsm_x4(bl[nj], bL + off);
                }
            }
#pragma unroll
            for (int mi = 0; mi < 4; mi++) {
                uint32_t ah[4], al[4];
                if (TRA) {
                    uint32_t off = (uint32_t)((kk + tr_krow) * PADT + wm + mi * 16 + tr_mcol) * 2;
                    ldsm_x4t(ah, aH + off);
                    ldsm_x4t(al, aL + off);
                } else {
                    uint32_t off = (uint32_t)((wm + mi * 16 + nt_row) * PADN + kk + nt_col) * 2;
                    ldsm_x4(ah, aH + off);
                    ldsm_x4(al, aL + off);
                }
#pragma unroll
                for (int ni = 0; ni < 4; ni++) {
                    uint32_t b0 = bh[ni >> 1][ni & 1], b1 = bh[ni >> 1][(ni & 1) + 2];
                    mma16816(acc[mi][ni], ah, b0, b1);
                    mma16816(acc[mi][ni], al, b0, b1);
                    mma16816(acc[mi][ni], ah, bl[ni >> 1][ni & 1], bl[ni >> 1][(ni & 1) + 2]);
                }
            }
        }
        if (s + 1 < NSTEP) { storeA(1 - buf); storeB(1 - buf); }
        __syncthreads();
    }

    // epilogue
    float* Cb = C + (size_t)blockIdx.z * strC;
#pragma unroll
    for (int mi = 0; mi < 4; mi++) {
#pragma unroll
        for (int ni = 0; ni < 4; ni++) {
            int n = n0 + wn + ni * 8 + (lane & 3) * 2;
            int m = m0 + wm + mi * 16 + (lane >> 2);
            float bx = 0.f, by = 0.f;
            if (bias) { float2 bv = *(const float2*)(bias + n); bx = bv.x; by = bv.y; }
            float* p0 = Cb + (size_t)m * ldc + n;
            float* p1 = Cb + (size_t)(m + 8) * ldc + n;
            p0[0] = acc[mi][ni][0] * scale + bx;  p0[1] = acc[mi][ni][1] * scale + by;
            p1[0] = acc[mi][ni][2] * scale + bx;  p1[1] = acc[mi][ni][3] * scale + by;
        }
    }
}

// ---------------------------------------------------------------------------
// softmax over K=256, in-place
// ---------------------------------------------------------------------------
__global__ __launch_bounds__(256)
void softmax256(float* __restrict__ S)
{
    int warp = threadIdx.x >> 5, lane = threadIdx.x & 31;
    size_t row = (size_t)blockIdx.x * 8 + warp;
    float* p = S + row * K_;

    float v[8];
    float m = -INFINITY;
#pragma unroll
    for (int i = 0; i < 8; i++) { v[i] = p[lane + i * 32]; m = fmaxf(m, v[i]); }
#pragma unroll
    for (int o = 16; o > 0; o >>= 1) m = fmaxf(m, __shfl_xor_sync(0xffffffffu, m, o));
    float s = 0.f;
#pragma unroll
    for (int i = 0; i < 8; i++) { v[i] = __expf(v[i] - m); s += v[i]; }
#pragma unroll
    for (int o = 16; o > 0; o >>= 1) s += __shfl_xor_sync(0xffffffffu, s, o);
    float inv = 1.f / s;
#pragma unroll
    for (int i = 0; i < 8; i++) p[lane + i * 32] = v[i] * inv;
}

// ---------------------------------------------------------------------------
extern "C" void kernel_launch(void* const* d_in, const int* in_sizes, int n_in,
                              void* d_out, int out_size)
{
    const float* x    = (const float*)d_in[0];   // [B,L,D]
    const float* W    = (const float*)d_in[1];   // [D,3D]
    const float* bias = (const float*)d_in[2];   // [3D]
    const float* Hk   = (const float*)d_in[3];   // [L,K]
    const float* Hv   = (const float*)d_in[4];   // [L,K]
    float*       out  = (float*)d_out;           // [B,L,D]

    float *qkv, *sc, *kp, *vp;
    cudaGetSymbolAddress((void**)&qkv, g_qkv);
    cudaGetSymbolAddress((void**)&sc,  g_sc);
    cudaGetSymbolAddress((void**)&kp,  g_kp);
    cudaGetSymbolAddress((void**)&vp,  g_vp);

    // dynamic smem sizes (bytes): 2 stages * (2*SA + 2*SB) * 2B
    const int SZ_NT = 2 * (2 * 128 * PADN + 2 * 32 * PADT) * 2;   // (0,1): 75776
    const int SZ_TT = 2 * (2 * 32 * PADT + 2 * 32 * PADT) * 2;    // (1,1): 69632
    const int SZ_NN = 2 * (2 * 128 * PADN + 2 * 128 * PADN) * 2;  // (0,0): 81920
    cudaFuncSetAttribute(gsplit<0,1>, cudaFuncAttributeMaxDynamicSharedMemorySize, SZ_NT);
    cudaFuncSetAttribute(gsplit<1,1>, cudaFuncAttributeMaxDynamicSharedMemorySize, SZ_TT);
    cudaFuncSetAttribute(gsplit<0,0>, cudaFuncAttributeMaxDynamicSharedMemorySize, SZ_NN);

    // 1) qkv[m,n] = x @ W + bias        A=[BL,1024] k-contig, B=W [1024,3072] n-contig
    gsplit<0,1><<<dim3(N3_ / 128, BL_ / 128, 1), 256, SZ_NT>>>(
        x, D_, 0L, W, N3_, 0L, qkv, N3_, 0L, D_, 1.f, bias);

    // 2) K_proj[kc,d] = Hk^T @ k        A=Hk [4096,256] m-contig, B=k slice [4096,·] n-contig
    gsplit<1,1><<<dim3(D_ / 128, K_ / 128, B_), 256, SZ_TT>>>(
        Hk, K_, 0L, qkv + D_, N3_, (long)L_ * N3_,
        kp, D_, (long)K_ * D_, L_, 1.f, nullptr);

    // 2') V_proj[kc,d] = Hv^T @ v
    gsplit<1,1><<<dim3(D_ / 128, K_ / 128, B_), 256, SZ_TT>>>(
        Hv, K_, 0L, qkv + 2 * D_, N3_, (long)L_ * N3_,
        vp, D_, (long)K_ * D_, L_, 1.f, nullptr);

    // 3) scores[l,kc] = q @ K_proj^T / 32   A=q slice k-contig, B=Kp [256,1024] k-contig
    gsplit<0,0><<<dim3(K_ / 128, L_ / 128, B_), 256, SZ_NN>>>(
        qkv, N3_, (long)L_ * N3_, kp, D_, (long)K_ * D_,
        sc, K_, (long)L_ * K_, D_, 0.03125f, nullptr);

    // 4) softmax
    softmax256<<<BL_ / 8, 256>>>(sc);

    // 5) out[l,d] = P @ V_proj          A=P [4096,256] k-contig, B=Vp [256,1024] n-contig
    gsplit<0,1><<<dim3(D_ / 128, L_ / 128, B_), 256, SZ_NT>>>(
        sc, K_, (long)L_ * K_, vp, D_, (long)K_ * D_,
        out, D_, (long)L_ * D_, K_, 1.f, nullptr);
}

// round 7
// speedup vs baseline: 1.7931x; 1.1505x over previous
#include <cuda_runtime.h>
#include <cuda_bf16.h>
#include <math.h>
#include <stdint.h>

#define B_  8
#define L_  4096
#define D_  1024
#define K_  256
#define N3_ 3072
#define BL_ (B_*L_)

typedef __nv_bfloat16 bf16;

// ---------------- scratch (__device__ globals) ------------------------------
__device__ bf16  g_xh [(size_t)BL_ * D_],  g_xl [(size_t)BL_ * D_];
__device__ bf16  g_wh [(size_t)D_ * N3_],  g_wl [(size_t)D_ * N3_];
__device__ bf16  g_hkh[(size_t)L_ * K_],   g_hkl[(size_t)L_ * K_];
__device__ bf16  g_hvh[(size_t)L_ * K_],   g_hvl[(size_t)L_ * K_];
__device__ bf16  g_qkvh[(size_t)BL_ * N3_], g_qkvl[(size_t)BL_ * N3_];
__device__ bf16  g_kph[(size_t)B_ * K_ * D_], g_kpl[(size_t)B_ * K_ * D_];
__device__ bf16  g_vph[(size_t)B_ * K_ * D_], g_vpl[(size_t)B_ * K_ * D_];
__device__ float g_sc [(size_t)BL_ * K_];
__device__ bf16  g_ph [(size_t)BL_ * K_],  g_pl [(size_t)BL_ * K_];

// ---------------- helpers ---------------------------------------------------
__device__ __forceinline__ uint32_t smem_u32(const void* p) {
    uint32_t a;
    asm("{ .reg .u64 t; cvta.to.shared.u64 t, %1; cvt.u32.u64 %0, t; }" : "=r"(a) : "l"(p));
    return a;
}
__device__ __forceinline__ void ldsm_x4(uint32_t* r, uint32_t addr) {
    asm volatile("ldmatrix.sync.aligned.m8n8.x4.shared.b16 {%0,%1,%2,%3}, [%4];"
                 : "=r"(r[0]), "=r"(r[1]), "=r"(r[2]), "=r"(r[3]) : "r"(addr));
}
__device__ __forceinline__ void ldsm_x4t(uint32_t* r, uint32_t addr) {
    asm volatile("ldmatrix.sync.aligned.m8n8.x4.trans.shared.b16 {%0,%1,%2,%3}, [%4];"
                 : "=r"(r[0]), "=r"(r[1]), "=r"(r[2]), "=r"(r[3]) : "r"(addr));
}
__device__ __forceinline__ void mma16816(float* d, const uint32_t* a, uint32_t b0, uint32_t b1) {
    asm volatile("mma.sync.aligned.m16n8k16.row.col.f32.bf16.bf16.f32 "
                 "{%0,%1,%2,%3}, {%4,%5,%6,%7}, {%8,%9}, {%0,%1,%2,%3};"
                 : "+f"(d[0]), "+f"(d[1]), "+f"(d[2]), "+f"(d[3])
                 : "r"(a[0]), "r"(a[1]), "r"(a[2]), "r"(a[3]), "r"(b0), "r"(b1));
}
// (a,b) fp32 pair -> hi bf16x2 bits + lo bf16x2 bits
__device__ __forceinline__ void pack_hl(float a, float b, uint32_t& h, uint32_t& l) {
    __nv_bfloat162 hv = __floats2bfloat162_rn(a, b);
    float2 hf = __bfloat1622float2(hv);
    __nv_bfloat162 lv = __floats2bfloat162_rn(a - hf.x, b - hf.y);
    h = *(uint32_t*)&hv;
    l = *(uint32_t*)&lv;
}

// ---------------------------------------------------------------------------
// presplit: fp32 array -> separate hi/lo bf16 arrays (4 elems / thread)
// ---------------------------------------------------------------------------
__global__ __launch_bounds__(256)
void presplit(const float* __restrict__ src, bf16* __restrict__ h, bf16* __restrict__ l)
{
    size_t i = ((size_t)blockIdx.x * 256 + threadIdx.x) * 4;
    float4 v = *(const float4*)(src + i);
    uint32_t h0, l0, h1, l1;
    pack_hl(v.x, v.y, h0, l0);
    pack_hl(v.z, v.w, h1, l1);
    *(uint2*)(h + i) = make_uint2(h0, h1);
    *(uint2*)(l + i) = make_uint2(l0, l1);
}

// ---------------------------------------------------------------------------
// Core bf16 hi/lo mma GEMM (3-combo split): C = scale*(A.B) (+bias)
//   TRA/TRB: operand stored [k][mn] (trans) vs [mn][k].
//   OUTBF:   1 -> emit hi/lo bf16 pair arrays, 0 -> fp32.
// CTA 128x128, K-step 32, double-buffered smem.
// ---------------------------------------------------------------------------
#define PADN 40
#define PADT 136

template<int TRA, int TRB, int OUTBF>
__device__ __forceinline__ void ghl_core(
    const bf16* __restrict__ Ah, const bf16* __restrict__ Al, int lda,
    const bf16* __restrict__ Bh, const bf16* __restrict__ Bl, int ldb,
    float* __restrict__ Cf, bf16* __restrict__ Ch, bf16* __restrict__ Cl, int ldc,
    int Kred, float scale, const float* __restrict__ bias, char* smem)
{
    constexpr int SAe = TRA ? 32 * PADT : 128 * PADN;
    constexpr int SBe = TRB ? 32 * PADT : 128 * PADN;
    constexpr int STE = 2 * SAe + 2 * SBe;

    const int tid = threadIdx.x, lane = tid & 31, warp = tid >> 5;
    const int wm = (warp & 1) * 64, wn = (warp >> 1) * 32;
    const int m0 = blockIdx.y * 128, n0 = blockIdx.x * 128;

    bf16* s0 = (bf16*)smem;
    const uint32_t sbase = smem_u32(s0);

    const int nt_row = lane & 15, nt_col = (lane >> 4) * 8;
    const int tr_krow = (lane & 7) + ((lane & 16) >> 1);
    const int tr_mcol = lane & 8;

    float acc[4][4][4] = {};
    uint4 pah[2], pal[2], pbh[2], pbl[2];

    auto loadAB = [&](int k0) {
#pragma unroll
        for (int i = 0; i < 2; i++) {
            int idx = tid + i * 256;
            if (TRA) {
                int kr = idx >> 4, c = (idx & 15) * 8;
                size_t o = (size_t)(k0 + kr) * lda + m0 + c;
                pah[i] = *(const uint4*)(Ah + o); pal[i] = *(const uint4*)(Al + o);
            } else {
                int r = idx >> 2, c = (idx & 3) * 8;
                size_t o = (size_t)(m0 + r) * lda + k0 + c;
                pah[i] = *(const uint4*)(Ah + o); pal[i] = *(const uint4*)(Al + o);
            }
            if (TRB) {
                int kr = idx >> 4, c = (idx & 15) * 8;
                size_t o = (size_t)(k0 + kr) * ldb + n0 + c;
                pbh[i] = *(const uint4*)(Bh + o); pbl[i] = *(const uint4*)(Bl + o);
            } else {
                int r = idx >> 2, c = (idx & 3) * 8;
                size_t o = (size_t)(n0 + r) * ldb + k0 + c;
                pbh[i] = *(const uint4*)(Bh + o); pbl[i] = *(const uint4*)(Bl + o);
            }
        }
    };
    auto storeAB = [&](int buf) {
        bf16* base = s0 + buf * STE;
#pragma unroll
        for (int i = 0; i < 2; i++) {
            int idx = tid + i * 256;
            int offA = TRA ? ((idx >> 4) * PADT + (idx & 15) * 8)
                           : ((idx >> 2) * PADN + (idx & 3) * 8);
            *(uint4*)(base + offA)       = pah[i];
            *(uint4*)(base + SAe + offA) = pal[i];
            int offB = TRB ? ((idx >> 4) * PADT + (idx & 15) * 8)
                           : ((idx >> 2) * PADN + (idx & 3) * 8);
            *(uint4*)(base + 2 * SAe + offB)       = pbh[i];
            *(uint4*)(base + 2 * SAe + SBe + offB) = pbl[i];
        }
    };

    loadAB(0);
    storeAB(0);
    __syncthreads();

    const int NSTEP = Kred / 32;
    for (int s = 0; s < NSTEP; s++) {
        const int buf = s & 1;
        if (s + 1 < NSTEP) loadAB((s + 1) * 32);

        const uint32_t aH = sbase + (uint32_t)(buf * STE) * 2;
        const uint32_t aL = aH + SAe * 2;
        const uint32_t bH = aH + 2 * SAe * 2;
        const uint32_t bL = bH + SBe * 2;

#pragma unroll
        for (int kk = 0; kk < 32; kk += 16) {
            uint32_t bh[2][4], bl[2][4];
#pragma unroll
            for (int nj = 0; nj < 2; nj++) {
                if (TRB) {
                    uint32_t off = (uint32_t)((kk + tr_krow) * PADT + wn + nj * 16 + tr_mcol) * 2;
                    ldsm_x4t(bh[nj], bH + off);
                    ldsm_x4t(bl[nj], bL + off);
                } else {
                    uint32_t off = (uint32_t)((wn + nj * 16 + nt_row) * PADN + kk + nt_col) * 2;
                    ldsm_x4(bh[nj], bH + off);
                    ldsm_x4(bl[nj], bL + off);
                }
            }
#pragma unroll
            for (int mi = 0; mi < 4; mi++) {
                uint32_t ah[4], al[4];
                if (TRA) {
                    uint32_t off = (uint32_t)((kk + tr_krow) * PADT + wm + mi * 16 + tr_mcol) * 2;
                    ldsm_x4t(ah, aH + off);
                    ldsm_x4t(al, aL + off);
                } else {
                    uint32_t off = (uint32_t)((wm + mi * 16 + nt_row) * PADN + kk + nt_col) * 2;
                    ldsm_x4(ah, aH + off);
                    ldsm_x4(al, aL + off);
                }
#pragma unroll
                for (int ni = 0; ni < 4; ni++) {
                    uint32_t b0 = bh[ni >> 1][ni & 1], b1 = bh[ni >> 1][(ni & 1) + 2];
                    mma16816(acc[mi][ni], ah, b0, b1);
                    mma16816(acc[mi][ni], al, b0, b1);
                    mma16816(acc[mi][ni], ah, bl[ni >> 1][ni & 1], bl[ni >> 1][(ni & 1) + 2]);
                }
            }
        }
        if (s + 1 < NSTEP) storeAB(1 - buf);
        __syncthreads();
    }

#pragma unroll
    for (int mi = 0; mi < 4; mi++) {
#pragma unroll
        for (int ni = 0; ni < 4; ni++) {
            int n = n0 + wn + ni * 8 + (lane & 3) * 2;
            int m = m0 + wm + mi * 16 + (lane >> 2);
            float bx = 0.f, by = 0.f;
            if (bias) { float2 bv = *(const float2*)(bias + n); bx = bv.x; by = bv.y; }
            float v00 = acc[mi][ni][0] * scale + bx, v01 = acc[mi][ni][1] * scale + by;
            float v10 = acc[mi][ni][2] * scale + bx, v11 = acc[mi][ni][3] * scale + by;
            if (OUTBF) {
                uint32_t h0, l0, h1, l1;
                pack_hl(v00, v01, h0, l0);
                pack_hl(v10, v11, h1, l1);
                *(uint32_t*)(Ch + (size_t)m * ldc + n)       = h0;
                *(uint32_t*)(Cl + (size_t)m * ldc + n)       = l0;
                *(uint32_t*)(Ch + (size_t)(m + 8) * ldc + n) = h1;
                *(uint32_t*)(Cl + (size_t)(m + 8) * ldc + n) = l1;
            } else {
                float* p0 = Cf + (size_t)m * ldc + n;
                float* p1 = Cf + (size_t)(m + 8) * ldc + n;
                p0[0] = v00; p0[1] = v01;
                p1[0] = v10; p1[1] = v11;
            }
        }
    }
}

// ---------------- wrappers --------------------------------------------------
__global__ __launch_bounds__(256, 2)
void k_gemm1(const bf16* xh, const bf16* xl, const bf16* wh, const bf16* wl,
             const float* bias, bf16* qkvh, bf16* qkvl)
{
    extern __shared__ char sm[];
    ghl_core<0, 1, 1>(xh, xl, D_, wh, wl, N3_,
                      nullptr, qkvh, qkvl, N3_, D_, 1.f, bias, sm);
}

__global__ __launch_bounds__(256, 2)
void k_proj(const bf16* hkh, const bf16* hkl, const bf16* hvh, const bf16* hvl,
            const bf16* qkvh, const bf16* qkvl,
            bf16* kph, bf16* kpl, bf16* vph, bf16* vpl)
{
    extern __shared__ char sm[];
    int p = blockIdx.z & 1, b = blockIdx.z >> 1;
    const bf16* Ah = p ? hvh : hkh;
    const bf16* Al = p ? hvl : hkl;
    const bf16* Bh = qkvh + (size_t)b * L_ * N3_ + (1 + p) * D_;
    const bf16* Bl = qkvl + (size_t)b * L_ * N3_ + (1 + p) * D_;
    bf16* Ch = (p ? vph : kph) + (size_t)b * K_ * D_;
    bf16* Cl = (p ? vpl : kpl) + (size_t)b * K_ * D_;
    ghl_core<1, 1, 1>(Ah, Al, K_, Bh, Bl, N3_,
                      nullptr, Ch, Cl, D_, L_, 1.f, nullptr, sm);
}

__global__ __launch_bounds__(256, 2)
void k_scores(const bf16* qkvh, const bf16* qkvl, const bf16* kph, const bf16* kpl,
              float* sc)
{
    extern __shared__ char sm[];
    int b = blockIdx.z;
    ghl_core<0, 0, 0>(qkvh + (size_t)b * L_ * N3_, qkvl + (size_t)b * L_ * N3_, N3_,
                      kph + (size_t)b * K_ * D_, kpl + (size_t)b * K_ * D_, D_,
                      sc + (size_t)b * L_ * K_, nullptr, nullptr, K_,
                      D_, 0.03125f, nullptr, sm);
}

__global__ __launch_bounds__(256, 2)
void k_out(const bf16* ph, const bf16* pl, const bf16* vph, const bf16* vpl,
           float* out)
{
    extern __shared__ char sm[];
    int b = blockIdx.z;
    ghl_core<0, 1, 0>(ph + (size_t)b * L_ * K_, pl + (size_t)b * L_ * K_, K_,
                      vph + (size_t)b * K_ * D_, vpl + (size_t)b * K_ * D_, D_,
                      out + (size_t)b * L_ * D_, nullptr, nullptr, D_,
                      K_, 1.f, nullptr, sm);
}

// ---------------------------------------------------------------------------
// softmax over K=256 -> hi/lo bf16 weights
// ---------------------------------------------------------------------------
__global__ __launch_bounds__(256)
void softmax_ps(const float* __restrict__ S, bf16* __restrict__ Ph, bf16* __restrict__ Pl)
{
    int warp = threadIdx.x >> 5, lane = threadIdx.x & 31;
    size_t row = (size_t)blockIdx.x * 8 + warp;
    const float* p = S + row * K_;

    float v[8];
    float m = -INFINITY;
#pragma unroll
    for (int i = 0; i < 8; i++) { v[i] = p[lane + i * 32]; m = fmaxf(m, v[i]); }
#pragma unroll
    for (int o = 16; o > 0; o >>= 1) m = fmaxf(m, __shfl_xor_sync(0xffffffffu, m, o));
    float s = 0.f;
#pragma unroll
    for (int i = 0; i < 8; i++) { v[i] = __expf(v[i] - m); s += v[i]; }
#pragma unroll
    for (int o = 16; o > 0; o >>= 1) s += __shfl_xor_sync(0xffffffffu, s, o);
    float inv = 1.f / s;
#pragma unroll
    for (int i = 0; i < 8; i++) {
        int kc = lane + i * 32;
        float w = v[i] * inv;
        bf16 h = __float2bfloat16_rn(w);
        bf16 lo = __float2bfloat16_rn(w - __bfloat162float(h));
        Ph[row * K_ + kc] = h;
        Pl[row * K_ + kc] = lo;
    }
}

// ---------------------------------------------------------------------------
extern "C" void kernel_launch(void* const* d_in, const int* in_sizes, int n_in,
                              void* d_out, int out_size)
{
    const float* x    = (const float*)d_in[0];
    const float* W    = (const float*)d_in[1];
    const float* bias = (const float*)d_in[2];
    const float* Hk   = (const float*)d_in[3];
    const float* Hv   = (const float*)d_in[4];
    float*       out  = (float*)d_out;

    bf16 *xh, *xl, *wh, *wl, *hkh, *hkl, *hvh, *hvl;
    bf16 *qkvh, *qkvl, *kph, *kpl, *vph, *vpl, *ph, *pl;
    float *sc;
    cudaGetSymbolAddress((void**)&xh, g_xh);   cudaGetSymbolAddress((void**)&xl, g_xl);
    cudaGetSymbolAddress((void**)&wh, g_wh);   cudaGetSymbolAddress((void**)&wl, g_wl);
    cudaGetSymbolAddress((void**)&hkh, g_hkh); cudaGetSymbolAddress((void**)&hkl, g_hkl);
    cudaGetSymbolAddress((void**)&hvh, g_hvh); cudaGetSymbolAddress((void**)&hvl, g_hvl);
    cudaGetSymbolAddress((void**)&qkvh, g_qkvh); cudaGetSymbolAddress((void**)&qkvl, g_qkvl);
    cudaGetSymbolAddress((void**)&kph, g_kph); cudaGetSymbolAddress((void**)&kpl, g_kpl);
    cudaGetSymbolAddress((void**)&vph, g_vph); cudaGetSymbolAddress((void**)&vpl, g_vpl);
    cudaGetSymbolAddress((void**)&ph, g_ph);   cudaGetSymbolAddress((void**)&pl, g_pl);
    cudaGetSymbolAddress((void**)&sc, g_sc);

    // dynamic smem: 2 stages * (2*SA + 2*SB) elems * 2B
    const int SZ_NT = 2 * (2 * 128 * PADN + 2 * 32 * PADT) * 2;   // 75776
    const int SZ_TT = 2 * (2 * 32 * PADT + 2 * 32 * PADT) * 2;    // 69632
    const int SZ_NN = 2 * (2 * 128 * PADN + 2 * 128 * PADN) * 2;  // 81920
    cudaFuncSetAttribute(k_gemm1,  cudaFuncAttributeMaxDynamicSharedMemorySize, SZ_NT);
    cudaFuncSetAttribute(k_proj,   cudaFuncAttributeMaxDynamicSharedMemorySize, SZ_TT);
    cudaFuncSetAttribute(k_scores, cudaFuncAttributeMaxDynamicSharedMemorySize, SZ_NN);
    cudaFuncSetAttribute(k_out,    cudaFuncAttributeMaxDynamicSharedMemorySize, SZ_NT);

    // 0) pre-split inputs into hi/lo bf16
    presplit<<<(size_t)BL_ * D_ / 1024, 256>>>(x, xh, xl);
    presplit<<<(size_t)D_ * N3_ / 1024, 256>>>(W, wh, wl);
    presplit<<<(size_t)L_ * K_ / 1024, 256>>>(Hk, hkh, hkl);
    presplit<<<(size_t)L_ * K_ / 1024, 256>>>(Hv, hvh, hvl);

    // 1) qkv = x @ W + bias  -> hi/lo bf16
    k_gemm1<<<dim3(N3_ / 128, BL_ / 128, 1), 256, SZ_NT>>>(xh, xl, wh, wl, bias, qkvh, qkvl);

    // 2) K_proj / V_proj = H^T @ {k,v} -> hi/lo bf16   (z = b*2+p, 256 CTAs)
    k_proj<<<dim3(D_ / 128, K_ / 128, 2 * B_), 256, SZ_TT>>>(
        hkh, hkl, hvh, hvl, qkvh, qkvl, kph, kpl, vph, vpl);

    // 3) scores = q @ K_proj^T / 32 -> fp32
    k_scores<<<dim3(K_ / 128, L_ / 128, B_), 256, SZ_NN>>>(qkvh, qkvl, kph, kpl, sc);

    // 4) softmax -> hi/lo bf16 weights
    softmax_ps<<<BL_ / 8, 256>>>(sc, ph, pl);

    // 5) out = P @ V_proj -> fp32
    k_out<<<dim3(D_ / 128, L_ / 128, B_), 256, SZ_NT>>>(ph, pl, vph, vpl, out);
}

// round 8
// speedup vs baseline: 1.9982x; 1.1144x over previous
#include <cuda_runtime.h>
#include <cuda_bf16.h>
#include <math.h>
#include <stdint.h>

#define B_  8
#define L_  4096
#define D_  1024
#define K_  256
#define N3_ 3072
#define BL_ (B_*L_)

typedef __nv_bfloat16 bf16;

// ---------------- scratch (__device__ globals) ------------------------------
__device__ bf16  g_xh [(size_t)BL_ * D_],  g_xl [(size_t)BL_ * D_];
__device__ bf16  g_wh [(size_t)D_ * N3_],  g_wl [(size_t)D_ * N3_];
__device__ bf16  g_hkh[(size_t)L_ * K_],   g_hkl[(size_t)L_ * K_];
__device__ bf16  g_hvh[(size_t)L_ * K_],   g_hvl[(size_t)L_ * K_];
__device__ bf16  g_qkvh[(size_t)BL_ * N3_], g_qkvl[(size_t)BL_ * N3_];
__device__ bf16  g_kph[(size_t)B_ * K_ * D_], g_kpl[(size_t)B_ * K_ * D_];
__device__ bf16  g_vph[(size_t)B_ * K_ * D_], g_vpl[(size_t)B_ * K_ * D_];
__device__ float g_sc [(size_t)BL_ * K_];
__device__ bf16  g_ph [(size_t)BL_ * K_],  g_pl [(size_t)BL_ * K_];

// ---------------- helpers ---------------------------------------------------
__device__ __forceinline__ uint32_t smem_u32(const void* p) {
    uint32_t a;
    asm("{ .reg .u64 t; cvta.to.shared.u64 t, %1; cvt.u32.u64 %0, t; }" : "=r"(a) : "l"(p));
    return a;
}
__device__ __forceinline__ void cp16(uint32_t saddr, const void* gaddr) {
    asm volatile("cp.async.cg.shared.global [%0], [%1], 16;" :: "r"(saddr), "l"(gaddr));
}
#define CP_COMMIT() asm volatile("cp.async.commit_group;" ::: "memory")
#define CP_WAIT0()  asm volatile("cp.async.wait_group 0;" ::: "memory")

__device__ __forceinline__ void ldsm_x4(uint32_t* r, uint32_t addr) {
    asm volatile("ldmatrix.sync.aligned.m8n8.x4.shared.b16 {%0,%1,%2,%3}, [%4];"
                 : "=r"(r[0]), "=r"(r[1]), "=r"(r[2]), "=r"(r[3]) : "r"(addr));
}
__device__ __forceinline__ void ldsm_x4t(uint32_t* r, uint32_t addr) {
    asm volatile("ldmatrix.sync.aligned.m8n8.x4.trans.shared.b16 {%0,%1,%2,%3}, [%4];"
                 : "=r"(r[0]), "=r"(r[1]), "=r"(r[2]), "=r"(r[3]) : "r"(addr));
}
__device__ __forceinline__ void mma16816(float* d, const uint32_t* a, uint32_t b0, uint32_t b1) {
    asm volatile("mma.sync.aligned.m16n8k16.row.col.f32.bf16.bf16.f32 "
                 "{%0,%1,%2,%3}, {%4,%5,%6,%7}, {%8,%9}, {%0,%1,%2,%3};"
                 : "+f"(d[0]), "+f"(d[1]), "+f"(d[2]), "+f"(d[3])
                 : "r"(a[0]), "r"(a[1]), "r"(a[2]), "r"(a[3]), "r"(b0), "r"(b1));
}
__device__ __forceinline__ void pack_hl(float a, float b, uint32_t& h, uint32_t& l) {
    __nv_bfloat162 hv = __floats2bfloat162_rn(a, b);
    float2 hf = __bfloat1622float2(hv);
    __nv_bfloat162 lv = __floats2bfloat162_rn(a - hf.x, b - hf.y);
    h = *(uint32_t*)&hv;
    l = *(uint32_t*)&lv;
}

// ---------------------------------------------------------------------------
// presplit: fp32 -> hi/lo bf16
// ---------------------------------------------------------------------------
__global__ __launch_bounds__(256)
void presplit(const float* __restrict__ src, bf16* __restrict__ h, bf16* __restrict__ l)
{
    size_t i = ((size_t)blockIdx.x * 256 + threadIdx.x) * 4;
    float4 v = *(const float4*)(src + i);
    uint32_t h0, l0, h1, l1;
    pack_hl(v.x, v.y, h0, l0);
    pack_hl(v.z, v.w, h1, l1);
    *(uint2*)(h + i) = make_uint2(h0, h1);
    *(uint2*)(l + i) = make_uint2(l0, l1);
}

// ---------------------------------------------------------------------------
// Core bf16 hi/lo mma GEMM, cp.async double-buffered.
// ---------------------------------------------------------------------------
#define PADN 40
#define PADT 136

template<int TRA, int TRB, int OUTBF>
__device__ __forceinline__ void ghl_core(
    const bf16* __restrict__ Ah, const bf16* __restrict__ Al, int lda,
    const bf16* __restrict__ Bh, const bf16* __restrict__ Bl, int ldb,
    float* __restrict__ Cf, bf16* __restrict__ Ch, bf16* __restrict__ Cl, int ldc,
    int Kred, float scale, const float* __restrict__ bias, char* smem)
{
    constexpr int SAe = TRA ? 32 * PADT : 128 * PADN;
    constexpr int SBe = TRB ? 32 * PADT : 128 * PADN;
    constexpr int STE = 2 * SAe + 2 * SBe;

    const int tid = threadIdx.x, lane = tid & 31, warp = tid >> 5;
    const int wm = (warp & 1) * 64, wn = (warp >> 1) * 32;
    const int m0 = blockIdx.y * 128, n0 = blockIdx.x * 128;

    const uint32_t sbase = smem_u32(smem);

    const int nt_row = lane & 15, nt_col = (lane >> 4) * 8;
    const int tr_krow = (lane & 7) + ((lane & 16) >> 1);
    const int tr_mcol = lane & 8;

    // per-thread copy slots (2 x 16B per tile-half)
    int aoff[2], boff[2];
    size_t agof[2], bgof[2];          // gmem offsets excluding k-term
#pragma unroll
    for (int i = 0; i < 2; i++) {
        int idx = tid + i * 256;
        if (TRA) { int kr = idx >> 4, c = (idx & 15) * 8;
            aoff[i] = kr * PADT + c;  agof[i] = (size_t)kr * lda + m0 + c; }
        else     { int r = idx >> 2,  c = (idx & 3) * 8;
            aoff[i] = r * PADN + c;   agof[i] = (size_t)(m0 + r) * lda + c; }
        if (TRB) { int kr = idx >> 4, c = (idx & 15) * 8;
            boff[i] = kr * PADT + c;  bgof[i] = (size_t)kr * ldb + n0 + c; }
        else     { int r = idx >> 2,  c = (idx & 3) * 8;
            boff[i] = r * PADN + c;   bgof[i] = (size_t)(n0 + r) * ldb + c; }
    }

    auto issue_stage = [&](int buf, int k0) {
        uint32_t base = sbase + (uint32_t)(buf * STE) * 2;
#pragma unroll
        for (int i = 0; i < 2; i++) {
            size_t ka = TRA ? (size_t)k0 * lda : (size_t)k0;
            size_t kb = TRB ? (size_t)k0 * ldb : (size_t)k0;
            cp16(base + (uint32_t)aoff[i] * 2,              Ah + agof[i] + ka);
            cp16(base + (uint32_t)(SAe + aoff[i]) * 2,      Al + agof[i] + ka);
            cp16(base + (uint32_t)(2 * SAe + boff[i]) * 2,  Bh + bgof[i] + kb);
            cp16(base + (uint32_t)(2 * SAe + SBe + boff[i]) * 2, Bl + bgof[i] + kb);
        }
        CP_COMMIT();
    };

    float acc[4][4][4] = {};

    issue_stage(0, 0);

    const int NSTEP = Kred / 32;
    for (int s = 0; s < NSTEP; s++) {
        const int buf = s & 1;
        CP_WAIT0();
        __syncthreads();
        if (s + 1 < NSTEP) issue_stage(1 - buf, (s + 1) * 32);

        const uint32_t aH = sbase + (uint32_t)(buf * STE) * 2;
        const uint32_t aL = aH + SAe * 2;
        const uint32_t bH = aH + 2 * SAe * 2;
        const uint32_t bL = bH + SBe * 2;

#pragma unroll
        for (int kk = 0; kk < 32; kk += 16) {
            uint32_t bh[2][4], bl[2][4];
#pragma unroll
            for (int nj = 0; nj < 2; nj++) {
                if (TRB) {
                    uint32_t off = (uint32_t)((kk + tr_krow) * PADT + wn + nj * 16 + tr_mcol) * 2;
                    ldsm_x4t(bh[nj], bH + off);
                    ldsm_x4t(bl[nj], bL + off);
                } else {
                    uint32_t off = (uint32_t)((wn + nj * 16 + nt_row) * PADN + kk + nt_col) * 2;
                    ldsm_x4(bh[nj], bH + off);
                    ldsm_x4(bl[nj], bL + off);
                }
            }
#pragma unroll
            for (int mi = 0; mi < 4; mi++) {
                uint32_t ah[4], al[4];
                if (TRA) {
                    uint32_t off = (uint32_t)((kk + tr_krow) * PADT + wm + mi * 16 + tr_mcol) * 2;
                    ldsm_x4t(ah, aH + off);
                    ldsm_x4t(al, aL + off);
                } else {
                    uint32_t off = (uint32_t)((wm + mi * 16 + nt_row) * PADN + kk + nt_col) * 2;
                    ldsm_x4(ah, aH + off);
                    ldsm_x4(al, aL + off);
                }
#pragma unroll
                for (int ni = 0; ni < 4; ni++) {
                    uint32_t b0 = bh[ni >> 1][ni & 1], b1 = bh[ni >> 1][(ni & 1) + 2];
                    mma16816(acc[mi][ni], ah, b0, b1);
                    mma16816(acc[mi][ni], al, b0, b1);
                    mma16816(acc[mi][ni], ah, bl[ni >> 1][ni & 1], bl[ni >> 1][(ni & 1) + 2]);
                }
            }
        }
        __syncthreads();
    }

#pragma unroll
    for (int mi = 0; mi < 4; mi++) {
#pragma unroll
        for (int ni = 0; ni < 4; ni++) {
            int n = n0 + wn + ni * 8 + (lane & 3) * 2;
            int m = m0 + wm + mi * 16 + (lane >> 2);
            float bx = 0.f, by = 0.f;
            if (bias) { float2 bv = *(const float2*)(bias + n); bx = bv.x; by = bv.y; }
            float v00 = acc[mi][ni][0] * scale + bx, v01 = acc[mi][ni][1] * scale + by;
            float v10 = acc[mi][ni][2] * scale + bx, v11 = acc[mi][ni][3] * scale + by;
            if (OUTBF) {
                uint32_t h0, l0, h1, l1;
                pack_hl(v00, v01, h0, l0);
                pack_hl(v10, v11, h1, l1);
                *(uint32_t*)(Ch + (size_t)m * ldc + n)       = h0;
                *(uint32_t*)(Cl + (size_t)m * ldc + n)       = l0;
                *(uint32_t*)(Ch + (size_t)(m + 8) * ldc + n) = h1;
                *(uint32_t*)(Cl + (size_t)(m + 8) * ldc + n) = l1;
            } else {
                float* p0 = Cf + (size_t)m * ldc + n;
                float* p1 = Cf + (size_t)(m + 8) * ldc + n;
                p0[0] = v00; p0[1] = v01;
                p1[0] = v10; p1[1] = v11;
            }
        }
    }
}

// ---------------- wrappers --------------------------------------------------
__global__ __launch_bounds__(256, 2)
void k_gemm1(const bf16* xh, const bf16* xl, const bf16* wh, const bf16* wl,
             const float* bias, bf16* qkvh, bf16* qkvl)
{
    extern __shared__ char sm[];
    ghl_core<0, 1, 1>(xh, xl, D_, wh, wl, N3_,
                      nullptr, qkvh, qkvl, N3_, D_, 1.f, bias, sm);
}

__global__ __launch_bounds__(256, 2)
void k_proj(const bf16* hkh, const bf16* hkl, const bf16* hvh, const bf16* hvl,
            const bf16* qkvh, const bf16* qkvl,
            bf16* kph, bf16* kpl, bf16* vph, bf16* vpl)
{
    extern __shared__ char sm[];
    int p = blockIdx.z & 1, b = blockIdx.z >> 1;
    const bf16* Ah = p ? hvh : hkh;
    const bf16* Al = p ? hvl : hkl;
    const bf16* Bh = qkvh + (size_t)b * L_ * N3_ + (1 + p) * D_;
    const bf16* Bl = qkvl + (size_t)b * L_ * N3_ + (1 + p) * D_;
    bf16* Ch = (p ? vph : kph) + (size_t)b * K_ * D_;
    bf16* Cl = (p ? vpl : kpl) + (size_t)b * K_ * D_;
    ghl_core<1, 1, 1>(Ah, Al, K_, Bh, Bl, N3_,
                      nullptr, Ch, Cl, D_, L_, 1.f, nullptr, sm);
}

__global__ __launch_bounds__(256, 2)
void k_scores(const bf16* qkvh, const bf16* qkvl, const bf16* kph, const bf16* kpl,
              float* sc)
{
    extern __shared__ char sm[];
    int b = blockIdx.z;
    ghl_core<0, 0, 0>(qkvh + (size_t)b * L_ * N3_, qkvl + (size_t)b * L_ * N3_, N3_,
                      kph + (size_t)b * K_ * D_, kpl + (size_t)b * K_ * D_, D_,
                      sc + (size_t)b * L_ * K_, nullptr, nullptr, K_,
                      D_, 0.03125f, nullptr, sm);
}

__global__ __launch_bounds__(256, 2)
void k_out(const bf16* ph, const bf16* pl, const bf16* vph, const bf16* vpl,
           float* out)
{
    extern __shared__ char sm[];
    int b = blockIdx.z;
    ghl_core<0, 1, 0>(ph + (size_t)b * L_ * K_, pl + (size_t)b * L_ * K_, K_,
                      vph + (size_t)b * K_ * D_, vpl + (size_t)b * K_ * D_, D_,
                      out + (size_t)b * L_ * D_, nullptr, nullptr, D_,
                      K_, 1.f, nullptr, sm);
}

// ---------------------------------------------------------------------------
// softmax over K=256 -> hi/lo bf16 weights
// ---------------------------------------------------------------------------
__global__ __launch_bounds__(256)
void softmax_ps(const float* __restrict__ S, bf16* __restrict__ Ph, bf16* __restrict__ Pl)
{
    int warp = threadIdx.x >> 5, lane = threadIdx.x & 31;
    size_t row = (size_t)blockIdx.x * 8 + warp;
    const float* p = S + row * K_;

    float v[8];
    float m = -INFINITY;
#pragma unroll
    for (int i = 0; i < 8; i++) { v[i] = p[lane + i * 32]; m = fmaxf(m, v[i]); }
#pragma unroll
    for (int o = 16; o > 0; o >>= 1) m = fmaxf(m, __shfl_xor_sync(0xffffffffu, m, o));
    float s = 0.f;
#pragma unroll
    for (int i = 0; i < 8; i++) { v[i] = __expf(v[i] - m); s += v[i]; }
#pragma unroll
    for (int o = 16; o > 0; o >>= 1) s += __shfl_xor_sync(0xffffffffu, s, o);
    float inv = 1.f / s;
#pragma unroll
    for (int i = 0; i < 8; i++) {
        int kc = lane + i * 32;
        float w = v[i] * inv;
        bf16 h = __float2bfloat16_rn(w);
        bf16 lo = __float2bfloat16_rn(w - __bfloat162float(h));
        Ph[row * K_ + kc] = h;
        Pl[row * K_ + kc] = lo;
    }
}

// ---------------------------------------------------------------------------
extern "C" void kernel_launch(void* const* d_in, const int* in_sizes, int n_in,
                              void* d_out, int out_size)
{
    const float* x    = (const float*)d_in[0];
    const float* W    = (const float*)d_in[1];
    const float* bias = (const float*)d_in[2];
    const float* Hk   = (const float*)d_in[3];
    const float* Hv   = (const float*)d_in[4];
    float*       out  = (float*)d_out;

    bf16 *xh, *xl, *wh, *wl, *hkh, *hkl, *hvh, *hvl;
    bf16 *qkvh, *qkvl, *kph, *kpl, *vph, *vpl, *ph, *pl;
    float *sc;
    cudaGetSymbolAddress((void**)&xh, g_xh);   cudaGetSymbolAddress((void**)&xl, g_xl);
    cudaGetSymbolAddress((void**)&wh, g_wh);   cudaGetSymbolAddress((void**)&wl, g_wl);
    cudaGetSymbolAddress((void**)&hkh, g_hkh); cudaGetSymbolAddress((void**)&hkl, g_hkl);
    cudaGetSymbolAddress((void**)&hvh, g_hvh); cudaGetSymbolAddress((void**)&hvl, g_hvl);
    cudaGetSymbolAddress((void**)&qkvh, g_qkvh); cudaGetSymbolAddress((void**)&qkvl, g_qkvl);
    cudaGetSymbolAddress((void**)&kph, g_kph); cudaGetSymbolAddress((void**)&kpl, g_kpl);
    cudaGetSymbolAddress((void**)&vph, g_vph); cudaGetSymbolAddress((void**)&vpl, g_vpl);
    cudaGetSymbolAddress((void**)&ph, g_ph);   cudaGetSymbolAddress((void**)&pl, g_pl);
    cudaGetSymbolAddress((void**)&sc, g_sc);

    const int SZ_NT = 2 * (2 * 128 * PADN + 2 * 32 * PADT) * 2;   // 75776
    const int SZ_TT = 2 * (2 * 32 * PADT + 2 * 32 * PADT) * 2;    // 69632
    const int SZ_NN = 2 * (2 * 128 * PADN + 2 * 128 * PADN) * 2;  // 81920
    cudaFuncSetAttribute(k_gemm1,  cudaFuncAttributeMaxDynamicSharedMemorySize, SZ_NT);
    cudaFuncSetAttribute(k_proj,   cudaFuncAttributeMaxDynamicSharedMemorySize, SZ_TT);
    cudaFuncSetAttribute(k_scores, cudaFuncAttributeMaxDynamicSharedMemorySize, SZ_NN);
    cudaFuncSetAttribute(k_out,    cudaFuncAttributeMaxDynamicSharedMemorySize, SZ_NT);

    presplit<<<(size_t)BL_ * D_ / 1024, 256>>>(x, xh, xl);
    presplit<<<(size_t)D_ * N3_ / 1024, 256>>>(W, wh, wl);
    presplit<<<(size_t)L_ * K_ / 1024, 256>>>(Hk, hkh, hkl);
    presplit<<<(size_t)L_ * K_ / 1024, 256>>>(Hv, hvh, hvl);

    k_gemm1<<<dim3(N3_ / 128, BL_ / 128, 1), 256, SZ_NT>>>(xh, xl, wh, wl, bias, qkvh, qkvl);

    k_proj<<<dim3(D_ / 128, K_ / 128, 2 * B_), 256, SZ_TT>>>(
        hkh, hkl, hvh, hvl, qkvh, qkvl, kph, kpl, vph, vpl);

    k_scores<<<dim3(K_ / 128, L_ / 128, B_), 256, SZ_NN>>>(qkvh, qkvl, kph, kpl, sc);

    softmax_ps<<<BL_ / 8, 256>>>(sc, ph, pl);

    k_out<<<dim3(D_ / 128, L_ / 128, B_), 256, SZ_NT>>>(ph, pl, vph, vpl, out);
}